// round 1
// baseline (speedup 1.0000x reference)
#include <cuda_runtime.h>
#include <cuda_bf16.h>

// EPG / RF-spoiled SPGR simulation.
// Layout: one warp per voxel. 50 states padded to 64; lane l owns states
// k = l (slot 0) and k = l + 32 (slot 1). All state lives in registers.
// RF rotation is per-state (per-lane FMA); the gradient shift is done with
// warp shuffles; padded states are masked to zero each pulse to reproduce
// the reference's 50-state truncation exactly.

#define FULLMASK 0xffffffffu

static __device__ __forceinline__ void rf_rot(
    float c2, float ca,
    float Ar, float Ai, float Bpr, float Bpi, float Cr, float Ci,
    float Fpr, float Fpi, float Fmr, float Fmi, float Zr, float Zi,
    float& oFpr, float& oFpi, float& oFmr, float& oFmi, float& oZr, float& oZi)
{
    // Fp' = c2*Fp + A*Fm + Bp*Z          (A = ep^2*s2, Bp = -i*ep*sa)
    oFpr = c2*Fpr + Ar*Fmr - Ai*Fmi + Bpr*Zr - Bpi*Zi;
    oFpi = c2*Fpi + Ar*Fmi + Ai*Fmr + Bpr*Zi + Bpi*Zr;
    // Fm' = conj(A)*Fp + c2*Fm + conj(Bp)*Z
    oFmr = Ar*Fpr + Ai*Fpi + c2*Fmr + Bpr*Zr + Bpi*Zi;
    oFmi = Ar*Fpi - Ai*Fpr + c2*Fmi + Bpr*Zi - Bpi*Zr;
    // Z'  = C*Fp + conj(C)*Fm + ca*Z     (C = -0.5i*em*sa)
    oZr  = Cr*Fpr - Ci*Fpi + Cr*Fmr + Ci*Fmi + ca*Zr;
    oZi  = Cr*Fpi + Ci*Fpr + Cr*Fmi - Ci*Fmr + ca*Zi;
}

__global__ void __launch_bounds__(256)
epg_kernel(const float* __restrict__ T1, const float* __restrict__ T2,
           const float* __restrict__ alpha, const float* __restrict__ TR,
           float* __restrict__ out, int n)
{
    int gtid = blockIdx.x * blockDim.x + threadIdx.x;
    int v    = gtid >> 5;
    int lane = threadIdx.x & 31;
    if (v >= n) return;

    const float TRv = TR[0];
    const float t1  = T1[v];
    const float t2  = T2[v];
    const float a   = alpha[v];

    const float E1 = expf(-TRv / t1);
    const float E2 = expf(-TRv / t2);
    float sh, ch;
    sincosf(0.5f * a, &sh, &ch);
    const float c2 = ch * ch;
    const float s2 = sh * sh;
    float sa, ca;
    sincosf(a, &sa, &ca);

    const float boost   = (lane == 0) ? (1.0f - E1) : 0.0f;  // (1-E1) recovery into Z[0]
    const bool  killFp1 = (lane >= 18);  // k = lane+32 >= 50
    const bool  killFm1 = (lane >= 17);  // k = lane+32 >= 49

    // State registers: slot0 = state lane, slot1 = state lane+32
    float Fp0r = 0.f, Fp0i = 0.f, Fp1r = 0.f, Fp1i = 0.f;
    float Fm0r = 0.f, Fm0i = 0.f, Fm1r = 0.f, Fm1i = 0.f;
    float Z0r  = (lane == 0) ? 1.0f : 0.0f, Z0i = 0.f;
    float Z1r  = 0.f, Z1i = 0.f;

    float phi = 0.0f, inc = 0.0f;
    const float SPOIL = 2.0420352248333655f;  // float32(deg2rad(117))

    float sig_r = 0.f, sig_i = 0.f;

    #pragma unroll 1
    for (int p = 0; p < 200; ++p) {
        float s, c;
        sincosf(phi, &s, &c);
        const float ep2r = c * c - s * s;   // ep^2
        const float ep2i = 2.0f * c * s;
        const float Ar = ep2r * s2, Ai = ep2i * s2;
        const float Bpr =  s * sa,  Bpi = -c * sa;        // -i*ep*sa
        const float Cr  = -0.5f * s * sa, Ci = -0.5f * c * sa;  // -0.5i*em*sa

        float nFp0r, nFp0i, nFm0r, nFm0i, nZ0r, nZ0i;
        rf_rot(c2, ca, Ar, Ai, Bpr, Bpi, Cr, Ci,
               Fp0r, Fp0i, Fm0r, Fm0i, Z0r, Z0i,
               nFp0r, nFp0i, nFm0r, nFm0i, nZ0r, nZ0i);
        float nFp1r, nFp1i, nFm1r, nFm1i, nZ1r, nZ1i;
        rf_rot(c2, ca, Ar, Ai, Bpr, Bpi, Cr, Ci,
               Fp1r, Fp1i, Fm1r, Fm1i, Z1r, Z1i,
               nFp1r, nFp1i, nFm1r, nFm1i, nZ1r, nZ1i);

        // Signal of the LAST pulse is |Fp_rf[0] * e^{-i phi}| = |Fp_rf[0]|
        sig_r = nFp0r;
        sig_i = nFp0i;

        // Relaxation (+ Z[0] recovery)
        Fp0r = nFp0r * E2;  Fp0i = nFp0i * E2;
        Fp1r = nFp1r * E2;  Fp1i = nFp1i * E2;
        Fm0r = nFm0r * E2;  Fm0i = nFm0i * E2;
        Fm1r = nFm1r * E2;  Fm1i = nFm1i * E2;
        Z0r  = fmaf(nZ0r, E1, boost);  Z0i = nZ0i * E1;
        Z1r  = nZ1r * E1;              Z1i = nZ1i * E1;

        // Gradient shift.
        // Fp'[0]   = Fm_relaxed[1];  Fp'[k] = Fp_relaxed[k-1]
        // Fm'[k]   = Fm_relaxed[k+1]; Fm'[49..] = 0; Fp'[50..] = 0
        const float specr = __shfl_sync(FULLMASK, Fm0r, 1);
        const float speci = __shfl_sync(FULLMASK, Fm0i, 1);
        const float up0r  = __shfl_up_sync(FULLMASK, Fp0r, 1);
        const float up0i  = __shfl_up_sync(FULLMASK, Fp0i, 1);
        const float up1r  = __shfl_up_sync(FULLMASK, Fp1r, 1);
        const float up1i  = __shfl_up_sync(FULLMASK, Fp1i, 1);
        const float b31r  = __shfl_sync(FULLMASK, Fp0r, 31);
        const float b31i  = __shfl_sync(FULLMASK, Fp0i, 31);
        const float dn0r  = __shfl_down_sync(FULLMASK, Fm0r, 1);
        const float dn0i  = __shfl_down_sync(FULLMASK, Fm0i, 1);
        const float dn1r  = __shfl_down_sync(FULLMASK, Fm1r, 1);
        const float dn1i  = __shfl_down_sync(FULLMASK, Fm1i, 1);
        const float w0r   = __shfl_sync(FULLMASK, Fm1r, 0);
        const float w0i   = __shfl_sync(FULLMASK, Fm1i, 0);

        Fp0r = (lane == 0) ? specr : up0r;
        Fp0i = (lane == 0) ? speci : up0i;
        Fp1r = killFp1 ? 0.0f : ((lane == 0) ? b31r : up1r);
        Fp1i = killFp1 ? 0.0f : ((lane == 0) ? b31i : up1i);
        Fm0r = (lane == 31) ? w0r : dn0r;
        Fm0i = (lane == 31) ? w0i : dn0i;
        Fm1r = killFm1 ? 0.0f : dn1r;
        Fm1i = killFm1 ? 0.0f : dn1i;

        // RF-spoiling quadratic phase (same fp32 op order as reference)
        inc += SPOIL;
        phi += inc;
    }

    if (lane == 0) {
        out[v] = sqrtf(sig_r * sig_r + sig_i * sig_i);
    }
}

extern "C" void kernel_launch(void* const* d_in, const int* in_sizes, int n_in,
                              void* d_out, int out_size)
{
    const float* T1    = (const float*)d_in[0];
    const float* T2    = (const float*)d_in[1];
    const float* alpha = (const float*)d_in[2];
    const float* TR    = (const float*)d_in[3];
    float* out = (float*)d_out;

    const int n = in_sizes[0];            // number of voxels (warps)
    const int threads = 256;              // 8 warps / block
    const int wpb = threads / 32;
    const int blocks = (n + wpb - 1) / wpb;
    epg_kernel<<<blocks, threads>>>(T1, T2, alpha, TR, out, n);
}

// round 2
// speedup vs baseline: 1.6424x; 1.6424x over previous
#include <cuda_runtime.h>

// EPG / RF-spoiled SPGR simulation, round 2.
//
// Layout: one warp per voxel; 50 states padded to 64; lane l owns the state
// PAIR {k=2l, k=2l+1}, kept packed as f32x2 so the RF rotation runs on
// fma.rn.f32x2 (FFMA2). Gradient shift-by-1 = half in-lane move + 1 shuffle
// per component (4 SHFL/pulse total). The per-pulse trig (warp-uniform AND
// voxel-independent) is precomputed by an init kernel into a __device__
// table that replicates the reference's exact fp32 phi accumulation.
// State truncation (Fp[k>=50]=0, Fm[k>=49]=0) is folded into per-lane E2
// relax multipliers (pre-shift kill sets are exactly equivalent).

#define FULLMASK 0xffffffffu
typedef unsigned long long u64;
#define NP 200

__device__ float4 g_trig[NP];

__global__ void trig_init_kernel() {
    int p = threadIdx.x + blockIdx.x * blockDim.x;
    if (p >= NP) return;
    const float SPOIL = 2.0420352248333655f;  // float32(deg2rad(117))
    float phi = 0.f, inc = 0.f;
    for (int j = 0; j < p; ++j) { inc += SPOIL; phi += inc; }  // exact ref order
    float s, c;
    sincosf(phi, &s, &c);
    g_trig[p] = make_float4(s, c, c * c - s * s, 2.f * c * s);
}

static __device__ __forceinline__ u64 pk2(float lo, float hi) {
    u64 r; asm("mov.b64 %0, {%1, %2};" : "=l"(r) : "f"(lo), "f"(hi)); return r;
}
static __device__ __forceinline__ void upk2(u64 v, float& lo, float& hi) {
    asm("mov.b64 {%0, %1}, %2;" : "=f"(lo), "=f"(hi) : "l"(v));
}
static __device__ __forceinline__ u64 f2fma(u64 a, u64 b, u64 c) {
    u64 d; asm("fma.rn.f32x2 %0, %1, %2, %3;" : "=l"(d) : "l"(a), "l"(b), "l"(c)); return d;
}
static __device__ __forceinline__ u64 f2mul(u64 a, u64 b) {
    u64 d; asm("mul.rn.f32x2 %0, %1, %2;" : "=l"(d) : "l"(a), "l"(b)); return d;
}

__global__ void __launch_bounds__(256)
epg_kernel(const float* __restrict__ T1, const float* __restrict__ T2,
           const float* __restrict__ alpha, const float* __restrict__ TR,
           float* __restrict__ out, int n)
{
    __shared__ float4 s_trig[NP];
    for (int i = threadIdx.x; i < NP; i += blockDim.x) s_trig[i] = g_trig[i];
    __syncthreads();

    const int v    = (blockIdx.x * blockDim.x + threadIdx.x) >> 5;
    const int lane = threadIdx.x & 31;
    if (v >= n) return;

    const float TRv = TR[0];
    const float E1  = expf(-TRv / T1[v]);
    const float E2  = expf(-TRv / T2[v]);
    const float a   = alpha[v];
    float sh, chh; sincosf(0.5f * a, &sh, &chh);
    const float c2 = chh * chh, s2 = sh * sh;
    float sa, ca; sincosf(a, &sa, &ca);

    // Pre-shift kill sets folded into relax: Fp kill k>=49, Fm kill k>=50
    // (equivalent to post-shift Fp[k>=50]=0, Fm[k>=49]=0).
    const int kLo = 2 * lane, kHi = 2 * lane + 1;
    const u64 E2Fp = pk2(kLo <= 48 ? E2 : 0.f, kHi <= 48 ? E2 : 0.f);
    const u64 E2Fm = pk2(kLo <= 49 ? E2 : 0.f, kHi <= 49 ? E2 : 0.f);
    const u64 E1p    = pk2(E1, E1);
    const u64 boostp = pk2(lane == 0 ? 1.f - E1 : 0.f, 0.f);
    const u64 C2p = pk2(c2, c2);
    const u64 CAp = pk2(ca, ca);

    // Packed state: {k=2l, k=2l+1} per register pair.
    u64 Fpr = 0, Fpi = 0, Fmr = 0, Fmi = 0;
    u64 Zr = pk2(lane == 0 ? 1.f : 0.f, 0.f), Zi = 0;

    #pragma unroll 2
    for (int p = 0; p < NP - 1; ++p) {
        const float4 t = s_trig[p];             // {sinφ, cosφ, cos2φ, sin2φ}
        const float Ar   = t.z * s2;            // (e^{2iφ} s2).re
        const float Ai   = t.w * s2;
        const float Bpr  = t.x * sa;            // (-i e^{iφ} sa).re = sa sinφ
        const float nBpi = t.y * sa;            // -Bpi = sa cosφ
        const float Cr   = -0.5f * Bpr;         // (-0.5i e^{-iφ} sa).re
        const float Ci   = -0.5f * nBpi;        // = -0.5 sa cosφ

        const u64 Arp  = pk2(Ar, Ar),     Aip   = pk2(Ai, Ai),   nAip  = pk2(-Ai, -Ai);
        const u64 Bprp = pk2(Bpr, Bpr),   Bpip  = pk2(-nBpi, -nBpi), nBpip = pk2(nBpi, nBpi);
        const u64 Crp  = pk2(Cr, Cr),     Cip   = pk2(Ci, Ci),   nCip  = pk2(-Ci, -Ci);

        // RF rotation (all packed FFMA2)
        u64 nFpr = f2mul(C2p, Fpr);
        nFpr = f2fma(Arp,  Fmr, nFpr);
        nFpr = f2fma(nAip, Fmi, nFpr);
        nFpr = f2fma(Bprp, Zr,  nFpr);
        nFpr = f2fma(nBpip, Zi, nFpr);

        u64 nFpi = f2mul(C2p, Fpi);
        nFpi = f2fma(Arp,  Fmi, nFpi);
        nFpi = f2fma(Aip,  Fmr, nFpi);
        nFpi = f2fma(Bprp, Zi,  nFpi);
        nFpi = f2fma(Bpip, Zr,  nFpi);

        u64 nFmr = f2mul(C2p, Fmr);
        nFmr = f2fma(Arp,  Fpr, nFmr);
        nFmr = f2fma(Aip,  Fpi, nFmr);
        nFmr = f2fma(Bprp, Zr,  nFmr);
        nFmr = f2fma(Bpip, Zi,  nFmr);

        u64 nFmi = f2mul(C2p, Fmi);
        nFmi = f2fma(Arp,  Fpi, nFmi);
        nFmi = f2fma(nAip, Fpr, nFmi);
        nFmi = f2fma(Bprp, Zi,  nFmi);
        nFmi = f2fma(nBpip, Zr, nFmi);

        u64 nZr = f2mul(CAp, Zr);
        nZr = f2fma(Crp,  Fpr, nZr);
        nZr = f2fma(nCip, Fpi, nZr);
        nZr = f2fma(Crp,  Fmr, nZr);
        nZr = f2fma(Cip,  Fmi, nZr);

        u64 nZi = f2mul(CAp, Zi);
        nZi = f2fma(Crp,  Fpi, nZi);
        nZi = f2fma(Cip,  Fpr, nZi);
        nZi = f2fma(Crp,  Fmi, nZi);
        nZi = f2fma(nCip, Fmr, nZi);

        // Relaxation (+ truncation masks folded into E2Fp/E2Fm) + Z0 recovery
        const u64 rFpr = f2mul(nFpr, E2Fp);
        const u64 rFpi = f2mul(nFpi, E2Fp);
        const u64 rFmr = f2mul(nFmr, E2Fm);
        const u64 rFmi = f2mul(nFmi, E2Fm);
        Zr = f2fma(nZr, E1p, boostp);
        Zi = f2mul(nZi, E1p);

        // Gradient shift.
        // Fp'[2l]   = Fp[2l-1] (prev lane hi; lane0: Fm[1] = my Fm hi)
        // Fp'[2l+1] = Fp[2l]   (my lo)
        // Fm'[2l]   = Fm[2l+1] (my hi)
        // Fm'[2l+1] = Fm[2l+2] (next lane lo; k=63 garbage already masked 0)
        float fplr, fphr, fpli, fphi_;
        upk2(rFpr, fplr, fphr); upk2(rFpi, fpli, fphi_);
        float fmlr, fmhr, fmli, fmhi;
        upk2(rFmr, fmlr, fmhr); upk2(rFmi, fmli, fmhi);

        float sur = __shfl_up_sync(FULLMASK, fphr, 1);
        float sui = __shfl_up_sync(FULLMASK, fphi_, 1);
        float sdr = __shfl_down_sync(FULLMASK, fmlr, 1);
        float sdi = __shfl_down_sync(FULLMASK, fmli, 1);

        if (lane == 0) { sur = fmhr; sui = fmhi; }
        Fpr = pk2(sur, fplr);
        Fpi = pk2(sui, fpli);
        Fmr = pk2(fmhr, sdr);
        Fmi = pk2(fmhi, sdi);
    }

    // Final pulse: only Fp_rf[0] is needed (lane 0, lo slot).
    {
        const float4 t = s_trig[NP - 1];
        const float Ar = t.z * s2, Ai = t.w * s2;
        const float Bpr = t.x * sa, Bpi = -(t.y * sa);
        float fp0r, fp0i, fm0r, fm0i, z0r, z0i, dum;
        upk2(Fpr, fp0r, dum); upk2(Fpi, fp0i, dum);
        upk2(Fmr, fm0r, dum); upk2(Fmi, fm0i, dum);
        upk2(Zr,  z0r,  dum); upk2(Zi,  z0i,  dum);
        const float sr = c2*fp0r + Ar*fm0r - Ai*fm0i + Bpr*z0r - Bpi*z0i;
        const float si = c2*fp0i + Ar*fm0i + Ai*fm0r + Bpr*z0i + Bpi*z0r;
        if (lane == 0) out[v] = sqrtf(sr * sr + si * si);
    }
}

extern "C" void kernel_launch(void* const* d_in, const int* in_sizes, int n_in,
                              void* d_out, int out_size)
{
    const float* T1    = (const float*)d_in[0];
    const float* T2    = (const float*)d_in[1];
    const float* alpha = (const float*)d_in[2];
    const float* TR    = (const float*)d_in[3];
    float* out = (float*)d_out;

    const int n = in_sizes[0];
    trig_init_kernel<<<1, 256>>>();
    const int threads = 256;  // 8 warps/block
    const int wpb = threads / 32;
    const int blocks = (n + wpb - 1) / wpb;
    epg_kernel<<<blocks, threads>>>(T1, T2, alpha, TR, out, n);
}

// round 4
// speedup vs baseline: 1.8184x; 1.1072x over previous
#include <cuda_runtime.h>

// EPG / RF-spoiled SPGR, round 3 (re-run after infra failure; unroll 2->4).
// - One warp per voxel; lane l holds packed state pair {k=2l, k=2l+1} (f32x2).
// - Rotation computed in S/D basis (S=Fp+Fm, D=Fp-Fm): 18 packed ops vs 30.
// - E2/E1 relaxation + the 0.5 recovery factor folded into per-pulse
//   coefficients; (1-E1) boost folded into the Z fma chain seed.
// - Trig table stored PRE-DUPLICATED as f32x2 pairs so packed coefficients
//   are formed by packed mul/fma straight off LDS.128 (no duplication MOVs).
// - State truncation (pre-shift: Fp[k>=49]=0, Fm[k>=50]=0) via 64-bit ANDs
//   on the ALU pipe.

#define FULLMASK 0xffffffffu
typedef unsigned long long u64;
#define NP 200

// table[2p]   = {sinφ, sinφ, cosφ, cosφ}
// table[2p+1] = {cos2φ, cos2φ, sin2φ, sin2φ}
__device__ ulonglong2 g_tab[2 * NP];

__global__ void trig_init_kernel() {
    int p = threadIdx.x + blockIdx.x * blockDim.x;
    if (p >= NP) return;
    const float SPOIL = 2.0420352248333655f;  // float32(deg2rad(117))
    float phi = 0.f, inc = 0.f;
    for (int j = 0; j < p; ++j) { inc += SPOIL; phi += inc; }  // exact ref order
    float s, c;
    sincosf(phi, &s, &c);
    float4* f4 = reinterpret_cast<float4*>(g_tab);
    f4[2 * p]     = make_float4(s, s, c, c);
    f4[2 * p + 1] = make_float4(c * c - s * s, c * c - s * s, 2.f * c * s, 2.f * c * s);
}

static __device__ __forceinline__ u64 pk2(float lo, float hi) {
    u64 r; asm("mov.b64 %0, {%1, %2};" : "=l"(r) : "f"(lo), "f"(hi)); return r;
}
static __device__ __forceinline__ void upk2(u64 v, float& lo, float& hi) {
    asm("mov.b64 {%0, %1}, %2;" : "=f"(lo), "=f"(hi) : "l"(v));
}
static __device__ __forceinline__ u64 f2fma(u64 a, u64 b, u64 c) {
    u64 d; asm("fma.rn.f32x2 %0, %1, %2, %3;" : "=l"(d) : "l"(a), "l"(b), "l"(c)); return d;
}
static __device__ __forceinline__ u64 f2mul(u64 a, u64 b) {
    u64 d; asm("mul.rn.f32x2 %0, %1, %2;" : "=l"(d) : "l"(a), "l"(b)); return d;
}
static __device__ __forceinline__ u64 f2add(u64 a, u64 b) {
    u64 d; asm("add.rn.f32x2 %0, %1, %2;" : "=l"(d) : "l"(a), "l"(b)); return d;
}

__global__ void __launch_bounds__(256)
epg_kernel(const float* __restrict__ T1, const float* __restrict__ T2,
           const float* __restrict__ alpha, const float* __restrict__ TR,
           float* __restrict__ out, int n)
{
    __shared__ ulonglong2 s_tab[2 * NP];
    for (int i = threadIdx.x; i < 2 * NP; i += blockDim.x) s_tab[i] = g_tab[i];
    __syncthreads();

    const int v    = (blockIdx.x * blockDim.x + threadIdx.x) >> 5;
    const int lane = threadIdx.x & 31;
    if (v >= n) return;

    const float TRv = TR[0];
    const float E1  = expf(-TRv / T1[v]);
    const float E2  = expf(-TRv / T2[v]);
    const float a   = alpha[v];
    float sh, chh; sincosf(0.5f * a, &sh, &chh);
    const float c2 = chh * chh, s2 = sh * sh;
    float sa, ca; sincosf(a, &sa, &ca);

    // Voxel-constant packed coefficients (E2h = E2/2 absorbs the S/D recovery 1/2).
    const float c2E2h = 0.5f * c2 * E2;
    const float s2E2h = 0.5f * s2 * E2;
    const float saE2  = sa * E2;
    const float saE1h = 0.5f * sa * E1;
    const float caE1  = ca * E1;
    const u64 c2E2hP  = pk2(c2E2h, c2E2h);
    const u64 s2E2hP  = pk2(s2E2h, s2E2h);
    const u64 ns2E2hP = pk2(-s2E2h, -s2E2h);
    const u64 saE2P   = pk2(saE2, saE2);
    const u64 nsaE2P  = pk2(-saE2, -saE2);
    const u64 saE1hP  = pk2(saE1h, saE1h);
    const u64 nsaE1hP = pk2(-saE1h, -saE1h);
    const u64 caE1P   = pk2(caE1, caE1);
    const u64 nOneP   = pk2(-1.f, -1.f);
    const u64 boostP  = pk2(lane == 0 ? 1.f - E1 : 0.f, 0.f);
    const u64 zeroP   = 0;

    // Truncation masks (pre-shift): Fp kill k>=49, Fm kill k>=50.
    const int kLo = 2 * lane, kHi = 2 * lane + 1;
    const u64 mFp = (kLo <= 48 ? 0xffffffffull : 0ull) | (kHi <= 48 ? 0xffffffff00000000ull : 0ull);
    const u64 mFm = (kLo <= 49 ? 0xffffffffull : 0ull) | (kHi <= 49 ? 0xffffffff00000000ull : 0ull);

    // Packed state {k=2l, k=2l+1}.
    u64 Fpr = 0, Fpi = 0, Fmr = 0, Fmi = 0;
    u64 Zr = pk2(lane == 0 ? 1.f : 0.f, 0.f), Zi = 0;

    #pragma unroll 4
    for (int p = 0; p < NP - 1; ++p) {
        const ulonglong2 A  = s_tab[2 * p];      // {sin,sin},{cos,cos}
        const ulonglong2 Bt = s_tab[2 * p + 1];  // {cos2,cos2},{sin2,sin2}
        const u64 sinP = A.x,  cosP = A.y;
        const u64 c2fP = Bt.x, s2fP = Bt.y;

        // Per-pulse packed coefficients (relax + 1/2 folded in):
        const u64 alp  = f2fma(s2E2hP,  c2fP, c2E2hP);  // E2h(c2 + s2 cos2φ)
        const u64 bet  = f2fma(ns2E2hP, c2fP, c2E2hP);  // E2h(c2 - s2 cos2φ)
        const u64 gAi  = f2mul(s2E2hP,  s2fP);          // E2h s2 sin2φ
        const u64 gnAi = f2mul(ns2E2hP, s2fP);
        const u64 gBr  = f2mul(saE2P,  sinP);           // E2 sa sinφ   (= E2h·2Bpr)
        const u64 gBi  = f2mul(nsaE2P, cosP);           // -E2 sa cosφ  (= E2h·2Bpi)
        const u64 gnBi = f2mul(saE2P,  cosP);
        const u64 gCr  = f2mul(nsaE1hP, sinP);          // E1·Cr = -0.5 sa E1 sinφ
        const u64 gCi  = f2mul(nsaE1hP, cosP);          // E1·Ci
        const u64 gnCi = f2mul(saE1hP,  cosP);

        // S/D basis
        const u64 Sr = f2add(Fpr, Fmr);
        const u64 Si = f2add(Fpi, Fmi);
        const u64 Dr = f2fma(nOneP, Fmr, Fpr);
        const u64 Di = f2fma(nOneP, Fmi, Fpi);

        // Rotated + relaxed sums/differences
        const u64 nSr = f2fma(gBr,  Zr, f2fma(gAi,  Di, f2mul(alp, Sr)));
        const u64 nSi = f2fma(gBr,  Zi, f2fma(gnAi, Dr, f2mul(alp, Si)));
        const u64 nDr = f2fma(gnBi, Zi, f2fma(gnAi, Si, f2mul(bet, Dr)));
        const u64 nDi = f2fma(gBi,  Zr, f2fma(gAi,  Sr, f2mul(bet, Di)));

        // Z row (E1 folded; boost seeded into the chain)
        Zr = f2fma(caE1P, Zr, f2fma(gnCi, Di, f2fma(gCr, Sr, boostP)));
        Zi = f2fma(caE1P, Zi, f2fma(gCi,  Dr, f2fma(gCr, Si, zeroP)));

        // Recover Fp/Fm (already relaxed), apply truncation masks (ALU)
        const u64 rFpr = f2add(nSr, nDr) & mFp;
        const u64 rFpi = f2add(nSi, nDi) & mFp;
        const u64 rFmr = f2fma(nOneP, nDr, nSr) & mFm;
        const u64 rFmi = f2fma(nOneP, nDi, nSi) & mFm;

        // Gradient shift:
        // Fp'[2l] = Fp[2l-1] (prev lane hi; lane0: Fm[1] = own Fm hi)
        // Fp'[2l+1] = Fp[2l] (own lo)
        // Fm'[2l] = Fm[2l+1] (own hi)
        // Fm'[2l+1] = Fm[2l+2] (next lane lo; OOB lane31 value already masked 0)
        float fplr, fphr, fpli, fphi_;
        upk2(rFpr, fplr, fphr); upk2(rFpi, fpli, fphi_);
        float fmlr, fmhr, fmli, fmhi;
        upk2(rFmr, fmlr, fmhr); upk2(rFmi, fmli, fmhi);

        float sur = __shfl_up_sync(FULLMASK, fphr, 1);
        float sui = __shfl_up_sync(FULLMASK, fphi_, 1);
        float sdr = __shfl_down_sync(FULLMASK, fmlr, 1);
        float sdi = __shfl_down_sync(FULLMASK, fmli, 1);

        if (lane == 0) { sur = fmhr; sui = fmhi; }
        Fpr = pk2(sur, fplr);
        Fpi = pk2(sui, fpli);
        Fmr = pk2(fmhr, sdr);
        Fmi = pk2(fmhi, sdi);
    }

    // Final pulse: only Fp_rf[0] needed (lane 0, lo slot), raw (un-relaxed).
    {
        const float4 tA = reinterpret_cast<const float4*>(s_tab)[2 * (NP - 1)];
        const float4 tB = reinterpret_cast<const float4*>(s_tab)[2 * (NP - 1) + 1];
        const float s = tA.x, c = tA.z, c2f = tB.x, s2f = tB.z;
        const float Ar = c2f * s2, Ai = s2f * s2;
        const float Bpr = s * sa, Bpi = -(c * sa);
        float fp0r, fp0i, fm0r, fm0i, z0r, z0i, dum;
        upk2(Fpr, fp0r, dum); upk2(Fpi, fp0i, dum);
        upk2(Fmr, fm0r, dum); upk2(Fmi, fm0i, dum);
        upk2(Zr,  z0r,  dum); upk2(Zi,  z0i,  dum);
        const float sr = c2 * fp0r + Ar * fm0r - Ai * fm0i + Bpr * z0r - Bpi * z0i;
        const float si = c2 * fp0i + Ar * fm0i + Ai * fm0r + Bpr * z0i + Bpi * z0r;
        if (lane == 0) out[v] = sqrtf(sr * sr + si * si);
    }
}

extern "C" void kernel_launch(void* const* d_in, const int* in_sizes, int n_in,
                              void* d_out, int out_size)
{
    const float* T1    = (const float*)d_in[0];
    const float* T2    = (const float*)d_in[1];
    const float* alpha = (const float*)d_in[2];
    const float* TR    = (const float*)d_in[3];
    float* out = (float*)d_out;

    const int n = in_sizes[0];
    trig_init_kernel<<<1, 256>>>();
    const int threads = 256;  // 8 warps/block
    const int wpb = threads / 32;
    const int blocks = (n + wpb - 1) / wpb;
    epg_kernel<<<blocks, threads>>>(T1, T2, alpha, TR, out, n);
}

// round 7
// speedup vs baseline: 2.1472x; 1.1808x over previous
#include <cuda_runtime.h>

// EPG / RF-spoiled SPGR: rotating-frame formulation (re-run; broker flaked).
// State (S, D, Z) with S = F̂p+F̂m, D = F̂p−F̂m in the frame
// F̂p = e^{-i phi_p} Fp, F̂m = e^{+i phi_p} Fm. RF pulse = real 2x2 mix of
// (D, Z); S invariant. Phase survives only as per-pulse unit factors
// e^{±i delta_p} (delta_p = phi_{p+1}-phi_p, exact fp32 subtraction) applied
// at the shift, plus e^{-2i phi_{p+1}} on the Fm[1]->Fp[0] element (lane-0
// local, no shuffle). One warp per voxel; lane l holds packed pair
// {k=2l, k=2l+1} (f32x2). Truncation (pre-shift: Fp kill k>=49, Fm kill
// k>=50) via 64-bit ANDs on the ALU pipe.

#define FULLMASK 0xffffffffu
typedef unsigned long long u64;
#define NP 200

// g_tab[2p]   = {cos d, cos d, sin d, sin d}   (d = delta_p)
// g_tab[2p+1] = {cos 2phi_{p+1}, sin 2phi_{p+1}, 0, 0}
__device__ ulonglong2 g_tab[2 * NP];

__global__ void trig_init_kernel() {
    int p = threadIdx.x + blockIdx.x * blockDim.x;
    if (p >= NP) return;
    const float SPOIL = 2.0420352248333655f;  // float32(deg2rad(117))
    float phi = 0.f, inc = 0.f;
    for (int j = 0; j < p; ++j) { inc += SPOIL; phi += inc; }   // phi_p, exact ref order
    float phin = phi + (inc + SPOIL);                            // phi_{p+1}
    float d = phin - phi;                                        // exact subtraction
    float sd, cd;  sincosf(d, &sd, &cd);
    float s2p, c2p; sincosf(2.0f * phin, &s2p, &c2p);
    float4* f4 = reinterpret_cast<float4*>(g_tab);
    f4[2 * p]     = make_float4(cd, cd, sd, sd);
    f4[2 * p + 1] = make_float4(c2p, s2p, 0.f, 0.f);
}

static __device__ __forceinline__ u64 pk2(float lo, float hi) {
    u64 r; asm("mov.b64 %0, {%1, %2};" : "=l"(r) : "f"(lo), "f"(hi)); return r;
}
static __device__ __forceinline__ void upk2(u64 v, float& lo, float& hi) {
    asm("mov.b64 {%0, %1}, %2;" : "=f"(lo), "=f"(hi) : "l"(v));
}
static __device__ __forceinline__ u64 f2fma(u64 a, u64 b, u64 c) {
    u64 d; asm("fma.rn.f32x2 %0, %1, %2, %3;" : "=l"(d) : "l"(a), "l"(b), "l"(c)); return d;
}
static __device__ __forceinline__ u64 f2mul(u64 a, u64 b) {
    u64 d; asm("mul.rn.f32x2 %0, %1, %2;" : "=l"(d) : "l"(a), "l"(b)); return d;
}
static __device__ __forceinline__ u64 f2add(u64 a, u64 b) {
    u64 d; asm("add.rn.f32x2 %0, %1, %2;" : "=l"(d) : "l"(a), "l"(b)); return d;
}

__global__ void __launch_bounds__(256)
epg_kernel(const float* __restrict__ T1, const float* __restrict__ T2,
           const float* __restrict__ alpha, const float* __restrict__ TR,
           float* __restrict__ out, int n)
{
    __shared__ ulonglong2 s_tab[2 * NP];
    for (int i = threadIdx.x; i < 2 * NP; i += blockDim.x) s_tab[i] = g_tab[i];
    __syncthreads();

    const int v    = (blockIdx.x * blockDim.x + threadIdx.x) >> 5;
    const int lane = threadIdx.x & 31;
    if (v >= n) return;

    const float TRv = TR[0];
    const float E1  = expf(-TRv / T1[v]);
    const float E2  = expf(-TRv / T2[v]);
    const float a   = alpha[v];
    float sa, ca; sincosf(a, &sa, &ca);

    const float E2h   = 0.5f * E2;
    const float sa2   = 2.0f * sa;
    const float saE1h = 0.5f * sa * E1;
    const float caE1  = ca * E1;

    const u64 caP     = pk2(ca, ca);
    const u64 sa2P    = pk2(sa2, sa2);
    const u64 nsa2P   = pk2(-sa2, -sa2);
    const u64 caE1P   = pk2(caE1, caE1);
    const u64 saE1hP  = pk2(saE1h, saE1h);
    const u64 nsaE1hP = pk2(-saE1h, -saE1h);
    const u64 E2hP    = pk2(E2h, E2h);
    const u64 nE2hP   = pk2(-E2h, -E2h);
    const u64 nOneP   = pk2(-1.f, -1.f);
    const u64 boostP  = pk2(lane == 0 ? 1.f - E1 : 0.f, 0.f);
    const u64 zeroP   = 0;

    // Truncation masks (pre-shift): Fp-path kill k>=49, Fm-path kill k>=50.
    const int kLo = 2 * lane, kHi = 2 * lane + 1;
    const u64 mFp = (kLo <= 48 ? 0xffffffffull : 0ull) | (kHi <= 48 ? 0xffffffff00000000ull : 0ull);
    const u64 mFm = (kLo <= 49 ? 0xffffffffull : 0ull) | (kHi <= 49 ? 0xffffffff00000000ull : 0ull);

    // Rotating-frame state {k=2l, k=2l+1}: S = F̂p+F̂m, D = F̂p-F̂m, Z.
    // Init: Fp=Fm=0, Z[0]=1 (phi_0 = 0, frame == lab).
    u64 Sr = 0, Si = 0, Dr = 0, Di = 0;
    u64 Zr = pk2(lane == 0 ? 1.f : 0.f, 0.f), Zi = 0;

    #pragma unroll 4
    for (int p = 0; p < NP - 1; ++p) {
        const ulonglong2 T = s_tab[2 * p];          // {cd,cd},{sd,sd}
        const u64 cdP = T.x, sdP = T.y;
        float sp_c, sp_s;                           // {cos 2phi', sin 2phi'}
        upk2(s_tab[2 * p + 1].x, sp_c, sp_s);

        // Per-pulse coefficients: A = E2h * e^{-i d}  (Ar=cA, Ai=-sA)
        const u64 cA  = f2mul(E2hP, cdP);
        const u64 sA  = f2mul(E2hP, sdP);
        const u64 nsA = f2mul(nE2hP, sdP);

        // RF rotation (frame): D'' = ca*D - 2i*sa*Z
        //   D''r = ca*Dr + sa2*Zi ; D''i = ca*Di - sa2*Zr
        const u64 DDr = f2fma(caP, Dr, f2mul(sa2P,  Zi));
        const u64 DDi = f2fma(caP, Di, f2mul(nsa2P, Zr));
        // Z_next = E1*(ca*Z - 0.5i*sa*D) + boost
        const u64 nZr = f2fma(caE1P, Zr, f2fma(saE1hP,  Di, boostP));
        const u64 nZi = f2fma(caE1P, Zi, f2fma(nsaE1hP, Dr, zeroP));

        // W = S + D'' (= 2*Fp_rf),  X = S - D'' (= 2*Fm_rf)
        const u64 Wr = f2add(Sr, DDr);
        const u64 Wi = f2add(Si, DDi);
        const u64 Xr = f2fma(nOneP, DDr, Sr);
        const u64 Xi = f2fma(nOneP, DDi, Si);

        // P = A (.) W = E2 e^{-i d} Fp_rf ;  Q = conj(A) (.) X = E2 e^{+i d} Fm_rf
        const u64 Pr = f2fma(sA,  Wi, f2mul(cA, Wr)) & mFp;
        const u64 Pi = f2fma(nsA, Wr, f2mul(cA, Wi)) & mFp;
        const u64 Qr = f2fma(nsA, Xi, f2mul(cA, Xr)) & mFm;
        const u64 Qi = f2fma(sA,  Xr, f2mul(cA, Xi)) & mFm;

        // Shift: Fp'[2l]=P[2l-1] (prev hi; lane0 -> spec), Fp'[2l+1]=P[2l] (own lo)
        //        Fm'[2l]=Q[2l+1] (own hi),  Fm'[2l+1]=Q[2l+2] (next lo)
        float Plo_r, Phi_r, Plo_i, Phi_i;
        upk2(Pr, Plo_r, Phi_r); upk2(Pi, Plo_i, Phi_i);
        float Qlo_r, Qhi_r, Qlo_i, Qhi_i;
        upk2(Qr, Qlo_r, Qhi_r); upk2(Qi, Qlo_i, Qhi_i);

        float su_r = __shfl_up_sync(FULLMASK, Phi_r, 1);
        float su_i = __shfl_up_sync(FULLMASK, Phi_i, 1);
        float sd_r = __shfl_down_sync(FULLMASK, Qlo_r, 1);
        float sd_i = __shfl_down_sync(FULLMASK, Qlo_i, 1);

        // lane0 Fp'[0] = Q[1] * e^{-2i phi_{p+1}}  (Q[1] = own hi word)
        const float spec_r = Qhi_r * sp_c + Qhi_i * sp_s;
        const float spec_i = Qhi_i * sp_c - Qhi_r * sp_s;
        if (lane == 0) { su_r = spec_r; su_i = spec_i; }

        const u64 Psh_r = pk2(su_r, Plo_r);
        const u64 Psh_i = pk2(su_i, Plo_i);
        const u64 Qsh_r = pk2(Qhi_r, sd_r);
        const u64 Qsh_i = pk2(Qhi_i, sd_i);

        Sr = f2add(Psh_r, Qsh_r);
        Si = f2add(Psh_i, Qsh_i);
        Dr = f2fma(nOneP, Qsh_r, Psh_r);
        Di = f2fma(nOneP, Qsh_i, Psh_i);
        Zr = nZr; Zi = nZi;
    }

    // Final pulse (p = NP-1): |signal| = |Fp_rf[0]| = |S + D''|[0] / 2
    {
        float Sr0, Si0, Dr0, Di0, Zr0, Zi0, dum;
        upk2(Sr, Sr0, dum); upk2(Si, Si0, dum);
        upk2(Dr, Dr0, dum); upk2(Di, Di0, dum);
        upk2(Zr, Zr0, dum); upk2(Zi, Zi0, dum);
        const float DDr0 = ca * Dr0 + sa2 * Zi0;
        const float DDi0 = ca * Di0 - sa2 * Zr0;
        const float Wr0 = Sr0 + DDr0;
        const float Wi0 = Si0 + DDi0;
        if (lane == 0) out[v] = 0.5f * sqrtf(Wr0 * Wr0 + Wi0 * Wi0);
    }
}

extern "C" void kernel_launch(void* const* d_in, const int* in_sizes, int n_in,
                              void* d_out, int out_size)
{
    const float* T1    = (const float*)d_in[0];
    const float* T2    = (const float*)d_in[1];
    const float* alpha = (const float*)d_in[2];
    const float* TR    = (const float*)d_in[3];
    float* out = (float*)d_out;

    const int n = in_sizes[0];
    trig_init_kernel<<<1, 256>>>();
    const int threads = 256;  // 8 warps/block
    const int wpb = threads / 32;
    const int blocks = (n + wpb - 1) / wpb;
    epg_kernel<<<blocks, threads>>>(T1, T2, alpha, TR, out, n);
}